// round 2
// baseline (speedup 1.0000x reference)
#include <cuda_runtime.h>
#include <math.h>

#define K_NODES 4096
#define SEQ_L   32
#define D_MODEL 128
#define D_FF    512
#define N_EDGES 65536
#define N_TOT_EDGES (N_EDGES + K_NODES)

// ---------------- scratch (static device memory; no runtime allocation) ----
__device__ float g_xt[K_NODES * SEQ_L * D_MODEL];   // temporal output
__device__ float g_h [K_NODES * SEQ_L * D_MODEL];   // GAT-transformed features
__device__ float g_as[K_NODES * SEQ_L];
__device__ float g_ad[K_NODES * SEQ_L];
__device__ int   g_cnt[K_NODES];
__device__ int   g_cur[K_NODES];
__device__ int   g_off[K_NODES + 1];
__device__ int   g_csr_src[N_TOT_EDGES];
__device__ int   g_is32;   // 1 if edge_index is int32-packed, 0 if int64

// ---------------- helpers ---------------------------------------------------
__device__ __forceinline__ float gelu_exact(float v) {
    return 0.5f * v * (1.0f + erff(v * 0.70710678118654752f));
}

// LayerNorm of 32 rows x 128 cols, 256 threads (8 warps, 4 rows each).
__device__ __forceinline__ void layernorm_32x128(const float* __restrict__ sin,
                                                 float* __restrict__ sout,
                                                 const float* __restrict__ g,
                                                 const float* __restrict__ b) {
    int warp = threadIdx.x >> 5, lane = threadIdx.x & 31;
    float4 gg = *(const float4*)(g + lane * 4);
    float4 bb = *(const float4*)(b + lane * 4);
    for (int r = warp; r < 32; r += 8) {
        float4 v = *(const float4*)(sin + r * 128 + lane * 4);
        float s  = v.x + v.y + v.z + v.w;
        float ss = v.x * v.x + v.y * v.y + v.z * v.z + v.w * v.w;
        #pragma unroll
        for (int o = 16; o; o >>= 1) {
            s  += __shfl_xor_sync(0xffffffffu, s, o);
            ss += __shfl_xor_sync(0xffffffffu, ss, o);
        }
        float m   = s * (1.0f / 128.0f);
        float var = ss * (1.0f / 128.0f) - m * m;
        float rs  = rsqrtf(var + 1e-5f);
        float4 o4;
        o4.x = (v.x - m) * rs * gg.x + bb.x;
        o4.y = (v.y - m) * rs * gg.y + bb.y;
        o4.z = (v.z - m) * rs * gg.z + bb.z;
        o4.w = (v.w - m) * rs * gg.w + bb.w;
        *(float4*)(sout + r * 128 + lane * 4) = o4;
    }
}

// C[32, 128cols at colOff] = A[32,K](smem) @ W[N,K]^T (+bias). 256 threads.
// Each thread: 8 rows x 2 cols. MODE: 0=store, 1=store(gelu), 2=accumulate.
template <int K, int MODE>
__device__ __forceinline__ void gemm_pass(const float* __restrict__ sA, int lda,
                                          const float* __restrict__ W,
                                          const float* __restrict__ bias,
                                          float* __restrict__ sD, int ldd,
                                          int colOff) {
    int t  = threadIdx.x;
    int j0 = colOff + (t & 63);
    int j1 = j0 + 64;
    int r0 = (t >> 6) * 8;
    float acc0[8], acc1[8];
    #pragma unroll
    for (int r = 0; r < 8; r++) { acc0[r] = 0.f; acc1[r] = 0.f; }
    const float* w0p = W + (size_t)j0 * K;
    const float* w1p = W + (size_t)j1 * K;
    #pragma unroll 4
    for (int d = 0; d < K; d += 4) {
        float4 w0 = *(const float4*)(w0p + d);
        float4 w1 = *(const float4*)(w1p + d);
        #pragma unroll
        for (int r = 0; r < 8; r++) {
            float4 a = *(const float4*)(sA + (r0 + r) * lda + d);
            acc0[r] += a.x * w0.x + a.y * w0.y + a.z * w0.z + a.w * w0.w;
            acc1[r] += a.x * w1.x + a.y * w1.y + a.z * w1.z + a.w * w1.w;
        }
    }
    float b0 = bias ? bias[j0] : 0.f;
    float b1 = bias ? bias[j1] : 0.f;
    #pragma unroll
    for (int r = 0; r < 8; r++) {
        float v0 = acc0[r] + b0, v1 = acc1[r] + b1;
        if (MODE == 1) { v0 = gelu_exact(v0); v1 = gelu_exact(v1); }
        if (MODE == 2) {
            sD[(r0 + r) * ldd + j0] += v0;
            sD[(r0 + r) * ldd + j1] += v1;
        } else {
            sD[(r0 + r) * ldd + j0] = v0;
            sD[(r0 + r) * ldd + j1] = v1;
        }
    }
}

// ---------------- temporal transformer: one block per node ------------------
// dyn smem: sx[32*128] sh[32*128] sbuf[32*512] ssc[32*32] = 25600 floats.
__global__ void __launch_bounds__(256, 2)
temporal_kernel(const float* __restrict__ x,
                const float* __restrict__ ln1_g, const float* __restrict__ ln1_b,
                const float* __restrict__ qkv_w, const float* __restrict__ qkv_b,
                const float* __restrict__ out_w, const float* __restrict__ out_b,
                const float* __restrict__ ln2_g, const float* __restrict__ ln2_b,
                const float* __restrict__ ff1_w, const float* __restrict__ ff1_b,
                const float* __restrict__ ff2_w, const float* __restrict__ ff2_b) {
    extern __shared__ float sm[];
    float* sx   = sm;                    // 4096
    float* sh   = sx + 32 * 128;         // 4096
    float* sbuf = sh + 32 * 128;         // 16384
    float* ssc  = sbuf + 32 * 512;       // 1024

    int node = blockIdx.x;
    int t    = threadIdx.x;
    const float* xg = x + (size_t)node * (32 * 128);

    for (int i = t; i < 32 * 128 / 4; i += 256)
        ((float4*)sx)[i] = ((const float4*)xg)[i];
    __syncthreads();

    // ---- LN1 -> sh
    layernorm_32x128(sx, sh, ln1_g, ln1_b);
    __syncthreads();

    // ---- qkv = sh @ qkv_w^T + b  -> sbuf[32][384] (stride 512)
    for (int c = 0; c < 384; c += 128)
        gemm_pass<128, 0>(sh, 128, qkv_w, qkv_b, sbuf, 512, c);
    __syncthreads();

    // ---- scores[i][j] = q_i . k_j / sqrt(128)
    {
        int i = t >> 3, j0 = (t & 7) * 4;
        float acc[4] = {0.f, 0.f, 0.f, 0.f};
        const float* qrow = sbuf + i * 512;
        #pragma unroll 4
        for (int d = 0; d < 128; d += 4) {
            float4 q = *(const float4*)(qrow + d);
            #pragma unroll
            for (int jj = 0; jj < 4; jj++) {
                float4 k4 = *(const float4*)(sbuf + (j0 + jj) * 512 + 128 + d);
                acc[jj] += q.x * k4.x + q.y * k4.y + q.z * k4.z + q.w * k4.w;
            }
        }
        const float scale = 0.08838834764831845f;  // 1/sqrt(128)
        #pragma unroll
        for (int jj = 0; jj < 4; jj++) ssc[i * 32 + j0 + jj] = acc[jj] * scale;
    }
    __syncthreads();

    // ---- softmax rows of ssc
    {
        int warp = t >> 5, lane = t & 31;
        for (int r = warp; r < 32; r += 8) {
            float v = ssc[r * 32 + lane];
            float mx = v;
            #pragma unroll
            for (int o = 16; o; o >>= 1) mx = fmaxf(mx, __shfl_xor_sync(0xffffffffu, mx, o));
            float e = expf(v - mx);
            float s = e;
            #pragma unroll
            for (int o = 16; o; o >>= 1) s += __shfl_xor_sync(0xffffffffu, s, o);
            ssc[r * 32 + lane] = e / s;
        }
    }
    __syncthreads();

    // ---- attn = a @ v  -> sh
    {
        int i = t >> 3, d0 = (t & 7) * 16;
        float acc[16];
        #pragma unroll
        for (int q = 0; q < 16; q++) acc[q] = 0.f;
        for (int j = 0; j < 32; j++) {
            float a = ssc[i * 32 + j];
            const float* vr = sbuf + j * 512 + 256 + d0;
            #pragma unroll
            for (int q = 0; q < 16; q += 4) {
                float4 v4 = *(const float4*)(vr + q);
                acc[q] += a * v4.x; acc[q + 1] += a * v4.y;
                acc[q + 2] += a * v4.z; acc[q + 3] += a * v4.w;
            }
        }
        #pragma unroll
        for (int q = 0; q < 16; q++) sh[i * 128 + d0 + q] = acc[q];
    }
    __syncthreads();

    // ---- x += attn @ out_w^T + out_b
    gemm_pass<128, 2>(sh, 128, out_w, out_b, sx, 128, 0);
    __syncthreads();

    // ---- LN2 -> sh
    layernorm_32x128(sx, sh, ln2_g, ln2_b);
    __syncthreads();

    // ---- ff1 + gelu -> sbuf[32][512]
    for (int c = 0; c < 512; c += 128)
        gemm_pass<128, 1>(sh, 128, ff1_w, ff1_b, sbuf, 512, c);
    __syncthreads();

    // ---- x += gelu(ff1) @ ff2_w^T + ff2_b
    gemm_pass<512, 2>(sbuf, 512, ff2_w, ff2_b, sx, 128, 0);
    __syncthreads();

    float* xtg = g_xt + (size_t)node * (32 * 128);
    for (int i = t; i < 32 * 128 / 4; i += 256)
        ((float4*)xtg)[i] = ((const float4*)sx)[i];
}

// ---------------- GAT transform: h = xt @ gat_w^T, plus a_src/a_dst --------
__global__ void __launch_bounds__(256)
gat_transform_kernel(const float* __restrict__ gat_w,
                     const float* __restrict__ att_src,
                     const float* __restrict__ att_dst) {
    __shared__ float sA[32 * 128];
    __shared__ float sD[32 * 128];
    int node = blockIdx.x, t = threadIdx.x;
    const float* xg = g_xt + (size_t)node * 4096;
    for (int i = t; i < 1024; i += 256)
        ((float4*)sA)[i] = ((const float4*)xg)[i];
    __syncthreads();

    gemm_pass<128, 0>(sA, 128, gat_w, (const float*)nullptr, sD, 128, 0);
    __syncthreads();

    float* hg = g_h + (size_t)node * 4096;
    for (int i = t; i < 1024; i += 256)
        ((float4*)hg)[i] = ((const float4*)sD)[i];

    int warp = t >> 5, lane = t & 31;
    float4 as4 = *(const float4*)(att_src + lane * 4);
    float4 ad4 = *(const float4*)(att_dst + lane * 4);
    for (int r = warp; r < 32; r += 8) {
        float4 h4 = *(const float4*)(sD + r * 128 + lane * 4);
        float s = h4.x * as4.x + h4.y * as4.y + h4.z * as4.z + h4.w * as4.w;
        float d = h4.x * ad4.x + h4.y * ad4.y + h4.z * ad4.z + h4.w * ad4.w;
        #pragma unroll
        for (int o = 16; o; o >>= 1) {
            s += __shfl_xor_sync(0xffffffffu, s, o);
            d += __shfl_xor_sync(0xffffffffu, d, o);
        }
        if (lane == 0) {
            g_as[node * 32 + r] = s;
            g_ad[node * 32 + r] = d;
        }
    }
}

// ---------------- edge dtype detection + CSR build ---------------------------
// If edge_index is int64 (little-endian, values < 4096), every odd int32 word
// within the first 2*N_EDGES words is a zero high-half. If it's int32, those
// words are random node ids (all-zero probability ~ 0).
__global__ void zero_counts_kernel() {
    int i = blockIdx.x * blockDim.x + threadIdx.x;
    if (i < K_NODES) { g_cnt[i] = 0; g_cur[i] = 0; }
    if (i == 0) g_is32 = 0;
}

__global__ void detect_dtype_kernel(const int* __restrict__ ei32) {
    int i = blockIdx.x * blockDim.x + threadIdx.x;
    if (i < N_EDGES) {
        if (ei32[2 * i + 1] != 0) atomicExch(&g_is32, 1);
    }
}

__device__ __forceinline__ int load_idx(const int* __restrict__ ei32, int elem) {
    return g_is32 ? ei32[elem] : ei32[2 * elem];
}

__global__ void count_edges_kernel(const int* __restrict__ ei32) {
    int e = blockIdx.x * blockDim.x + threadIdx.x;
    if (e >= N_TOT_EDGES) return;
    int dst = (e < N_EDGES) ? load_idx(ei32, N_EDGES + e) : (e - N_EDGES);
    if ((unsigned)dst >= K_NODES) return;
    atomicAdd(&g_cnt[dst], 1);
}

__global__ void scan_kernel() {  // 1 block, 1024 threads; 4096 counts
    __shared__ int ts[1024];
    int t = threadIdx.x;
    int c[4], s = 0;
    #pragma unroll
    for (int i = 0; i < 4; i++) { c[i] = s; s += g_cnt[t * 4 + i]; }
    ts[t] = s;
    __syncthreads();
    for (int o = 1; o < 1024; o <<= 1) {
        int v = (t >= o) ? ts[t - o] : 0;
        __syncthreads();
        ts[t] += v;
        __syncthreads();
    }
    int base = (t == 0) ? 0 : ts[t - 1];
    #pragma unroll
    for (int i = 0; i < 4; i++) g_off[t * 4 + i] = base + c[i];
    if (t == 1023) g_off[4096] = ts[1023];
}

__global__ void fill_edges_kernel(const int* __restrict__ ei32) {
    int e = blockIdx.x * blockDim.x + threadIdx.x;
    if (e >= N_TOT_EDGES) return;
    int src, dst;
    if (e < N_EDGES) {
        src = load_idx(ei32, e);
        dst = load_idx(ei32, N_EDGES + e);
    } else {
        src = dst = e - N_EDGES;
    }
    if ((unsigned)dst >= K_NODES || (unsigned)src >= K_NODES) return;
    int pos = atomicAdd(&g_cur[dst], 1);
    g_csr_src[g_off[dst] + pos] = src;
}

// ---------------- GAT aggregation: one block per dst node -------------------
__global__ void __launch_bounds__(256)
gat_aggregate_kernel(const float* __restrict__ gat_b, float* __restrict__ out) {
    __shared__ float sm_m[32], sm_d[32];
    __shared__ float part[8][32];
    int dst = blockIdx.x, t = threadIdx.x;
    int off0 = g_off[dst], ne = g_cur[dst];

    // phase A: per-l max of leaky_relu(a_s[src]+a_d[dst])
    {
        int l = t & 31, grp = t >> 5;
        float adl = g_ad[dst * 32 + l];
        float lm = -3.4e38f;
        for (int e = grp; e < ne; e += 8) {
            int src = g_csr_src[off0 + e];
            float v = g_as[src * 32 + l] + adl;
            v = v > 0.f ? v : 0.2f * v;
            lm = fmaxf(lm, v);
        }
        part[grp][l] = lm;
        __syncthreads();
        if (t < 32) {
            float m = part[0][t];
            #pragma unroll
            for (int g2 = 1; g2 < 8; g2++) m = fmaxf(m, part[g2][t]);
            sm_m[t] = m;
        }
        __syncthreads();
    }
    // phase B: denom
    {
        int l = t & 31, grp = t >> 5;
        float adl = g_ad[dst * 32 + l];
        float m = sm_m[l], sden = 0.f;
        for (int e = grp; e < ne; e += 8) {
            int src = g_csr_src[off0 + e];
            float v = g_as[src * 32 + l] + adl;
            v = v > 0.f ? v : 0.2f * v;
            sden += expf(v - m);
        }
        __syncthreads();  // part[] reuse
        part[grp][l] = sden;
        __syncthreads();
        if (t < 32) {
            float s2 = 0.f;
            #pragma unroll
            for (int g2 = 0; g2 < 8; g2++) s2 += part[g2][t];
            sm_d[t] = s2;
        }
        __syncthreads();
    }
    // phase C: out[dst,l,d] = sum_e (ex/denom) * h[src,l,d] + gat_b[d]
    {
        int l = t >> 3, d0 = (t & 7) * 16;
        float m = sm_m[l];
        float adl = g_ad[dst * 32 + l];
        float acc[16];
        #pragma unroll
        for (int i = 0; i < 16; i++) acc[i] = 0.f;
        for (int e = 0; e < ne; e++) {
            int src = g_csr_src[off0 + e];
            float v = g_as[src * 32 + l] + adl;
            v = v > 0.f ? v : 0.2f * v;
            float ex = expf(v - m);
            const float4* hp = (const float4*)(g_h + ((size_t)src * 32 + l) * 128 + d0);
            #pragma unroll
            for (int q = 0; q < 4; q++) {
                float4 h4 = hp[q];
                acc[q * 4 + 0] += ex * h4.x;
                acc[q * 4 + 1] += ex * h4.y;
                acc[q * 4 + 2] += ex * h4.z;
                acc[q * 4 + 3] += ex * h4.w;
            }
        }
        float inv = 1.f / (sm_d[l] + 1e-16f);
        float* op = out + ((size_t)dst * 32 + l) * 128 + d0;
        #pragma unroll
        for (int q = 0; q < 4; q++) {
            float4 o4;
            o4.x = acc[q * 4 + 0] * inv + gat_b[d0 + q * 4 + 0];
            o4.y = acc[q * 4 + 1] * inv + gat_b[d0 + q * 4 + 1];
            o4.z = acc[q * 4 + 2] * inv + gat_b[d0 + q * 4 + 2];
            o4.w = acc[q * 4 + 3] * inv + gat_b[d0 + q * 4 + 3];
            ((float4*)op)[q] = o4;
        }
    }
}

// ---------------- launch -----------------------------------------------------
extern "C" void kernel_launch(void* const* d_in, const int* in_sizes, int n_in,
                              void* d_out, int out_size) {
    const float* x     = (const float*)d_in[0];
    const int*   ei32  = (const int*)d_in[1];   // int32 or int64 words; auto-detected
    const float* ln1_g = (const float*)d_in[2];
    const float* ln1_b = (const float*)d_in[3];
    const float* qkv_w = (const float*)d_in[4];
    const float* qkv_b = (const float*)d_in[5];
    const float* out_w = (const float*)d_in[6];
    const float* out_b = (const float*)d_in[7];
    const float* ln2_g = (const float*)d_in[8];
    const float* ln2_b = (const float*)d_in[9];
    const float* ff1_w = (const float*)d_in[10];
    const float* ff1_b = (const float*)d_in[11];
    const float* ff2_w = (const float*)d_in[12];
    const float* ff2_b = (const float*)d_in[13];
    const float* gat_w = (const float*)d_in[14];
    const float* att_s = (const float*)d_in[15];
    const float* att_d = (const float*)d_in[16];
    const float* gat_b = (const float*)d_in[17];
    float* out = (float*)d_out;

    const int TEMP_SMEM = 25600 * sizeof(float);  // 100 KB
    cudaFuncSetAttribute(temporal_kernel,
                         cudaFuncAttributeMaxDynamicSharedMemorySize, TEMP_SMEM);

    temporal_kernel<<<K_NODES, 256, TEMP_SMEM>>>(
        x, ln1_g, ln1_b, qkv_w, qkv_b, out_w, out_b,
        ln2_g, ln2_b, ff1_w, ff1_b, ff2_w, ff2_b);

    gat_transform_kernel<<<K_NODES, 256>>>(gat_w, att_s, att_d);

    zero_counts_kernel<<<(K_NODES + 255) / 256, 256>>>();
    detect_dtype_kernel<<<(N_EDGES + 255) / 256, 256>>>(ei32);
    count_edges_kernel<<<(N_TOT_EDGES + 255) / 256, 256>>>(ei32);
    scan_kernel<<<1, 1024>>>();
    fill_edges_kernel<<<(N_TOT_EDGES + 255) / 256, 256>>>(ei32);

    gat_aggregate_kernel<<<K_NODES, 256>>>(gat_b, out);
}